// round 1
// baseline (speedup 1.0000x reference)
#include <cuda_runtime.h>
#include <cuda_bf16.h>

// Problem constants (fixed by the reference)
#define Nn   10000      // nodes
#define Ee   80000      // edges (excl. self loops)
#define Gg   16         // B*DAYS graphs
#define HC   128        // H*C_OUT
#define NEG  0.2f

// ---- device scratch (allocation-free rule: __device__ globals) ----
__device__ __align__(16) float g_emb_proj[Nn * HC];   // embedding @ W   [N,128]
__device__ __align__(16) float g_asrc[Nn * 4];        // per-row src logits [N,H]
__device__ __align__(16) float g_adst[Nn * 4];        // per-row dst logits [N,H]
__device__ int g_row_ptr[Nn + 1];
__device__ int g_cursor[Nn];
__device__ int g_edge_src[Ee];

// ---------------- CSR build ----------------
__global__ void k_zero() {
    int i = blockIdx.x * blockDim.x + threadIdx.x;
    if (i < Nn) g_cursor[i] = 0;
}

__global__ void k_hist(const int* __restrict__ adj) {
    int e = blockIdx.x * blockDim.x + threadIdx.x;
    if (e < Ee) atomicAdd(&g_cursor[adj[Ee + e]], 1);  // adj[1] = dst
}

// single-block exclusive scan of g_cursor[0..N) -> g_row_ptr; copy into g_cursor
__global__ void k_scan() {
    const int CH = 10;  // 1024*10 >= 10000
    __shared__ int part[1024];
    int t = threadIdx.x;
    int base = t * CH;
    int loc[CH];
    int sum = 0;
#pragma unroll
    for (int i = 0; i < CH; i++) {
        int idx = base + i;
        int v = (idx < Nn) ? g_cursor[idx] : 0;
        loc[i] = sum;
        sum += v;
    }
    part[t] = sum;
    __syncthreads();
    for (int off = 1; off < 1024; off <<= 1) {
        int v = (t >= off) ? part[t - off] : 0;
        __syncthreads();
        part[t] += v;
        __syncthreads();
    }
    int prev = (t > 0) ? part[t - 1] : 0;
#pragma unroll
    for (int i = 0; i < CH; i++) {
        int idx = base + i;
        if (idx < Nn) {
            int p = prev + loc[i];
            g_row_ptr[idx] = p;
            g_cursor[idx] = p;
        }
    }
    if (t == 0) g_row_ptr[Nn] = part[1023];
}

__global__ void k_fill(const int* __restrict__ adj) {
    int e = blockIdx.x * blockDim.x + threadIdx.x;
    if (e < Ee) {
        int d = adj[Ee + e];
        int p = atomicAdd(&g_cursor[d], 1);
        g_edge_src[p] = adj[e];  // adj[0] = src
    }
}

// ---------------- projection: emb_proj = embedding @ W ; per-row logits ----------------
// one block (128 threads) per embedding row
__global__ void k_proj(const float* __restrict__ emb, const float* __restrict__ W,
                       const float* __restrict__ att_s, const float* __restrict__ att_d) {
    int n = blockIdx.x;
    int c = threadIdx.x;  // 0..127, channel; head h = c>>5
    __shared__ float se[32];
    if (c < 32) se[c] = emb[n * 32 + c];
    __syncthreads();
    float acc = 0.f;
#pragma unroll
    for (int k = 0; k < 32; k++) acc = fmaf(se[k], W[k * 128 + c], acc);
    g_emb_proj[n * 128 + c] = acc;
    // attention logits: dot of this head's 32 channels with att vectors
    int h = c >> 5, lane = c & 31;
    float vs = acc * att_s[c];   // att_src flat [H*C] matches channel index
    float vd = acc * att_d[c];
#pragma unroll
    for (int o = 16; o > 0; o >>= 1) {
        vs += __shfl_down_sync(0xffffffffu, vs, o);
        vd += __shfl_down_sync(0xffffffffu, vd, o);
    }
    if (lane == 0) {
        g_asrc[n * 4 + h] = vs;
        g_adst[n * 4 + h] = vd;
    }
}

// ---------------- main GAT kernel: one warp per (graph, dst node) ----------------
// Lane l owns channels [4l, 4l+3] (all within head h = l>>3) -> float4 accum,
// scalar per-lane online-softmax state (m, s) for its head.
__global__ void __launch_bounds__(256) k_gat(const int* __restrict__ x,
                                             const float* __restrict__ bias,
                                             float* __restrict__ out) {
    int w = (blockIdx.x * blockDim.x + threadIdx.x) >> 5;
    int lane = threadIdx.x & 31;
    if (w >= Gg * Nn) return;
    int g = w / Nn;
    int v = w - g * Nn;
    const int* __restrict__ xg = x + g * Nn;

    int vemb = xg[v];
    int h = lane >> 3;
    float adst = g_adst[vemb * 4 + h];

    // self loop initializes the online softmax
    float a0 = g_asrc[vemb * 4 + h] + adst;
    a0 = fmaxf(a0, NEG * a0);  // leaky relu
    float m = a0, s = 1.f;
    float4 acc = *(const float4*)(g_emb_proj + vemb * 128 + 4 * lane);

    int beg = g_row_ptr[v], end = g_row_ptr[v + 1];
    for (int idx = beg; idx < end; idx++) {
        int j = g_edge_src[idx];
        int u = xg[j];
        float a = g_asrc[u * 4 + h] + adst;
        a = fmaxf(a, NEG * a);
        float4 msg = *(const float4*)(g_emb_proj + u * 128 + 4 * lane);
        float nm = fmaxf(m, a);
        float c1 = __expf(m - nm);
        float c2 = __expf(a - nm);
        s = s * c1 + c2;
        acc.x = acc.x * c1 + c2 * msg.x;
        acc.y = acc.y * c1 + c2 * msg.y;
        acc.z = acc.z * c1 + c2 * msg.z;
        acc.w = acc.w * c1 + c2 * msg.w;
        m = nm;
    }

    float inv = 1.f / (s + 1e-16f);
    float4 b = *(const float4*)(bias + 4 * lane);
    float4 o;
    o.x = acc.x * inv + b.x;
    o.y = acc.y * inv + b.y;
    o.z = acc.z * inv + b.z;
    o.w = acc.w * inv + b.w;
    *(float4*)(out + ((size_t)g * Nn + v) * 128 + 4 * lane) = o;
}

extern "C" void kernel_launch(void* const* d_in, const int* in_sizes, int n_in,
                              void* d_out, int out_size) {
    const int*   x     = (const int*)d_in[0];     // [B,DAYS,N] = [16,10000]
    const int*   adj   = (const int*)d_in[1];     // [2,E]
    const float* emb   = (const float*)d_in[2];   // [N,32]
    const float* W     = (const float*)d_in[3];   // [32,128]
    const float* att_s = (const float*)d_in[4];   // [4,32]
    const float* att_d = (const float*)d_in[5];   // [4,32]
    const float* bias  = (const float*)d_in[6];   // [128]
    float* out = (float*)d_out;                   // [16,10000,128]

    k_zero<<<(Nn + 255) / 256, 256>>>();
    k_hist<<<(Ee + 255) / 256, 256>>>(adj);
    k_scan<<<1, 1024>>>();
    k_fill<<<(Ee + 255) / 256, 256>>>(adj);
    k_proj<<<Nn, 128>>>(emb, W, att_s, att_d);

    int total_threads = Gg * Nn * 32;
    k_gat<<<(total_threads + 255) / 256, 256>>>(x, bias, out);
}

// round 2
// speedup vs baseline: 1.1772x; 1.1772x over previous
#include <cuda_runtime.h>
#include <cuda_fp16.h>

// Problem constants (fixed by the reference)
#define Nn   10000      // nodes
#define Ee   80000      // edges (excl. self loops)
#define Gg   16         // B*DAYS graphs
#define HC   128        // H*C_OUT
#define NEG  0.2f

// ---- device scratch (allocation-free rule: __device__ globals) ----
__device__ __align__(16) __half g_emb_h[Nn * HC];     // fp16 projected embedding [N,128]
__device__ __align__(16) float g_asrc[Nn * 4];        // per-row src logits [N,H]
__device__ __align__(16) float g_adst[Nn * 4];        // per-row dst logits [N,H]
__device__ int g_row_ptr[Nn + 1];
__device__ int g_cursor[Nn];
__device__ int g_edge_src[Ee];

// ---------------- CSR build ----------------
__global__ void k_zero() {
    int i = blockIdx.x * blockDim.x + threadIdx.x;
    if (i < Nn) g_cursor[i] = 0;
}

__global__ void k_hist(const int* __restrict__ adj) {
    int e = blockIdx.x * blockDim.x + threadIdx.x;
    if (e < Ee) atomicAdd(&g_cursor[adj[Ee + e]], 1);  // adj[1] = dst
}

// single-block exclusive scan of g_cursor[0..N) -> g_row_ptr; copy into g_cursor
__global__ void k_scan() {
    const int CH = 10;  // 1024*10 >= 10000
    __shared__ int part[1024];
    int t = threadIdx.x;
    int base = t * CH;
    int loc[CH];
    int sum = 0;
#pragma unroll
    for (int i = 0; i < CH; i++) {
        int idx = base + i;
        int v = (idx < Nn) ? g_cursor[idx] : 0;
        loc[i] = sum;
        sum += v;
    }
    part[t] = sum;
    __syncthreads();
    for (int off = 1; off < 1024; off <<= 1) {
        int v = (t >= off) ? part[t - off] : 0;
        __syncthreads();
        part[t] += v;
        __syncthreads();
    }
    int prev = (t > 0) ? part[t - 1] : 0;
#pragma unroll
    for (int i = 0; i < CH; i++) {
        int idx = base + i;
        if (idx < Nn) {
            int p = prev + loc[i];
            g_row_ptr[idx] = p;
            g_cursor[idx] = p;
        }
    }
    if (t == 0) g_row_ptr[Nn] = part[1023];
}

__global__ void k_fill(const int* __restrict__ adj) {
    int e = blockIdx.x * blockDim.x + threadIdx.x;
    if (e < Ee) {
        int d = adj[Ee + e];
        int p = atomicAdd(&g_cursor[d], 1);
        g_edge_src[p] = adj[e];  // adj[0] = src
    }
}

// ---------------- projection: emb_proj = embedding @ W (fp16) ; per-row logits (fp32) ----------------
// one block (128 threads) per embedding row
__global__ void k_proj(const float* __restrict__ emb, const float* __restrict__ W,
                       const float* __restrict__ att_s, const float* __restrict__ att_d) {
    int n = blockIdx.x;
    int c = threadIdx.x;  // 0..127, channel; head h = c>>5
    __shared__ float se[32];
    if (c < 32) se[c] = emb[n * 32 + c];
    __syncthreads();
    float acc = 0.f;
#pragma unroll
    for (int k = 0; k < 32; k++) acc = fmaf(se[k], W[k * 128 + c], acc);
    g_emb_h[n * 128 + c] = __float2half(acc);
    // attention logits: dot of this head's 32 channels with att vectors (fp32)
    int h = c >> 5, lane = c & 31;
    float vs = acc * att_s[c];
    float vd = acc * att_d[c];
#pragma unroll
    for (int o = 16; o > 0; o >>= 1) {
        vs += __shfl_down_sync(0xffffffffu, vs, o);
        vd += __shfl_down_sync(0xffffffffu, vd, o);
    }
    if (lane == 0) {
        g_asrc[n * 4 + h] = vs;
        g_adst[n * 4 + h] = vd;
    }
}

// ---------------- main GAT kernel: one warp per (graph, dst node) ----------------
// Lane l owns channels [4l, 4l+3] (within head h = l>>3). fp16 message gathers,
// fp32 logits/accumulation, plain-exp softmax (logits are O(1), no overflow risk),
// edge loop unrolled x2 for MLP on the edge_src -> x -> emb pointer chase.
__device__ __forceinline__ void load_msg(int u, int lane, float4& f) {
    const __half2* p = (const __half2*)(g_emb_h + u * 128 + 4 * lane);
    __half2 m0 = p[0], m1 = p[1];
    float2 a = __half22float2(m0), b = __half22float2(m1);
    f.x = a.x; f.y = a.y; f.z = b.x; f.w = b.y;
}

__global__ void __launch_bounds__(256) k_gat(const int* __restrict__ x,
                                             const float* __restrict__ bias,
                                             float* __restrict__ out) {
    int w = (blockIdx.x * blockDim.x + threadIdx.x) >> 5;
    int lane = threadIdx.x & 31;
    if (w >= Gg * Nn) return;
    int g = w / Nn;
    int v = w - g * Nn;
    const int* __restrict__ xg = x + g * Nn;

    int vemb = xg[v];
    int h = lane >> 3;
    float adst = g_adst[vemb * 4 + h];

    // self loop initializes the accumulator
    float a0 = g_asrc[vemb * 4 + h] + adst;
    a0 = fmaxf(a0, NEG * a0);  // leaky relu
    float e0 = __expf(a0);
    float s = e0;
    float4 m;
    load_msg(vemb, lane, m);
    float4 acc;
    acc.x = e0 * m.x; acc.y = e0 * m.y; acc.z = e0 * m.z; acc.w = e0 * m.w;

    int idx = g_row_ptr[v];
    int end = g_row_ptr[v + 1];
    for (; idx + 2 <= end; idx += 2) {
        int j0 = g_edge_src[idx];
        int j1 = g_edge_src[idx + 1];
        int u0 = xg[j0];
        int u1 = xg[j1];
        float aa0 = g_asrc[u0 * 4 + h] + adst;
        float aa1 = g_asrc[u1 * 4 + h] + adst;
        float4 m0, m1;
        load_msg(u0, lane, m0);
        load_msg(u1, lane, m1);
        aa0 = fmaxf(aa0, NEG * aa0);
        aa1 = fmaxf(aa1, NEG * aa1);
        float w0 = __expf(aa0);
        float w1 = __expf(aa1);
        s += w0 + w1;
        acc.x = fmaf(w0, m0.x, fmaf(w1, m1.x, acc.x));
        acc.y = fmaf(w0, m0.y, fmaf(w1, m1.y, acc.y));
        acc.z = fmaf(w0, m0.z, fmaf(w1, m1.z, acc.z));
        acc.w = fmaf(w0, m0.w, fmaf(w1, m1.w, acc.w));
    }
    if (idx < end) {
        int j0 = g_edge_src[idx];
        int u0 = xg[j0];
        float aa0 = g_asrc[u0 * 4 + h] + adst;
        float4 m0;
        load_msg(u0, lane, m0);
        aa0 = fmaxf(aa0, NEG * aa0);
        float w0 = __expf(aa0);
        s += w0;
        acc.x = fmaf(w0, m0.x, acc.x);
        acc.y = fmaf(w0, m0.y, acc.y);
        acc.z = fmaf(w0, m0.z, acc.z);
        acc.w = fmaf(w0, m0.w, acc.w);
    }

    float inv = 1.f / (s + 1e-16f);
    float4 b = *(const float4*)(bias + 4 * lane);
    float4 o;
    o.x = fmaf(acc.x, inv, b.x);
    o.y = fmaf(acc.y, inv, b.y);
    o.z = fmaf(acc.z, inv, b.z);
    o.w = fmaf(acc.w, inv, b.w);
    *(float4*)(out + ((size_t)g * Nn + v) * 128 + 4 * lane) = o;
}

extern "C" void kernel_launch(void* const* d_in, const int* in_sizes, int n_in,
                              void* d_out, int out_size) {
    const int*   x     = (const int*)d_in[0];     // [B,DAYS,N] = [16,10000]
    const int*   adj   = (const int*)d_in[1];     // [2,E]
    const float* emb   = (const float*)d_in[2];   // [N,32]
    const float* W     = (const float*)d_in[3];   // [32,128]
    const float* att_s = (const float*)d_in[4];   // [4,32]
    const float* att_d = (const float*)d_in[5];   // [4,32]
    const float* bias  = (const float*)d_in[6];   // [128]
    float* out = (float*)d_out;                   // [16,10000,128]

    k_zero<<<(Nn + 255) / 256, 256>>>();
    k_hist<<<(Ee + 255) / 256, 256>>>(adj);
    k_scan<<<1, 1024>>>();
    k_fill<<<(Ee + 255) / 256, 256>>>(adj);
    k_proj<<<Nn, 128>>>(emb, W, att_s, att_d);

    int total_threads = Gg * Nn * 32;
    k_gat<<<(total_threads + 255) / 256, 256>>>(x, bias, out);
}

// round 3
// speedup vs baseline: 1.2306x; 1.0453x over previous
#include <cuda_runtime.h>
#include <cuda_fp16.h>

// Problem constants (fixed by the reference)
#define Nn   10000      // nodes
#define Ee   80000      // edges (excl. self loops)
#define Gg   16         // B*DAYS graphs
#define HC   128        // H*C_OUT
#define NEG  0.2f
#define GC   4          // graphs per warp in k_gat

// ---- device scratch (allocation-free rule: __device__ globals) ----
__device__ __align__(16) __half g_emb_h[Nn * HC];     // fp16 projected embedding [N,128]
__device__ __align__(16) float g_asrc[Nn * 4];        // per-row src logits [N,H]
__device__ __align__(16) float g_adst[Nn * 4];        // per-row dst logits [N,H]
__device__ __align__(16) int g_xT[Nn * Gg];           // transposed x: [N,16]
__device__ int g_row_ptr[Nn + 1];
__device__ int g_cursor[Nn];                          // INVARIANT: all-zero at kernel_launch entry
__device__ int g_edge_src[Ee];

// ---------------- CSR build ----------------
// g_cursor is zero on entry (zero-init at load; re-zeroed by k_proj each launch)
__global__ void k_hist(const int* __restrict__ adj) {
    int e = blockIdx.x * blockDim.x + threadIdx.x;
    if (e < Ee) atomicAdd(&g_cursor[adj[Ee + e]], 1);  // adj[1] = dst
}

// single-block exclusive scan of g_cursor[0..N) -> g_row_ptr; copy into g_cursor
__global__ void k_scan() {
    const int CH = 10;  // 1024*10 >= 10000
    __shared__ int part[1024];
    int t = threadIdx.x;
    int base = t * CH;
    int loc[CH];
    int sum = 0;
#pragma unroll
    for (int i = 0; i < CH; i++) {
        int idx = base + i;
        int v = (idx < Nn) ? g_cursor[idx] : 0;
        loc[i] = sum;
        sum += v;
    }
    part[t] = sum;
    __syncthreads();
    for (int off = 1; off < 1024; off <<= 1) {
        int v = (t >= off) ? part[t - off] : 0;
        __syncthreads();
        part[t] += v;
        __syncthreads();
    }
    int prev = (t > 0) ? part[t - 1] : 0;
#pragma unroll
    for (int i = 0; i < CH; i++) {
        int idx = base + i;
        if (idx < Nn) {
            int p = prev + loc[i];
            g_row_ptr[idx] = p;
            g_cursor[idx] = p;
        }
    }
    if (t == 0) g_row_ptr[Nn] = part[1023];
}

__global__ void k_fill(const int* __restrict__ adj) {
    int e = blockIdx.x * blockDim.x + threadIdx.x;
    if (e < Ee) {
        int d = adj[Ee + e];
        int p = atomicAdd(&g_cursor[d], 1);
        g_edge_src[p] = adj[e];  // adj[0] = src
    }
}

// ---------------- projection + x transpose + cursor reset ----------------
// one block (128 threads) per embedding row n
__global__ void k_proj(const float* __restrict__ emb, const float* __restrict__ W,
                       const float* __restrict__ att_s, const float* __restrict__ att_d,
                       const int* __restrict__ x) {
    int n = blockIdx.x;
    int c = threadIdx.x;  // 0..127, channel; head h = c>>5
    // side duties: reset cursor invariant, transpose x
    if (c == 0) g_cursor[n] = 0;
    if (c < Gg) g_xT[n * Gg + c] = x[c * Nn + n];
    __shared__ float se[32];
    if (c < 32) se[c] = emb[n * 32 + c];
    __syncthreads();
    float acc = 0.f;
#pragma unroll
    for (int k = 0; k < 32; k++) acc = fmaf(se[k], W[k * 128 + c], acc);
    g_emb_h[n * 128 + c] = __float2half(acc);
    // attention logits: dot of this head's 32 channels with att vectors (fp32)
    int h = c >> 5, lane = c & 31;
    float vs = acc * att_s[c];
    float vd = acc * att_d[c];
#pragma unroll
    for (int o = 16; o > 0; o >>= 1) {
        vs += __shfl_down_sync(0xffffffffu, vs, o);
        vd += __shfl_down_sync(0xffffffffu, vd, o);
    }
    if (lane == 0) {
        g_asrc[n * 4 + h] = vs;
        g_adst[n * 4 + h] = vd;
    }
}

// ---------------- main GAT kernel: one warp per (4-graph chunk, dst node) ----------------
// Lane l owns channels [4l, 4l+3] (within head h = l>>3) for 4 graphs.
// fp16 message gathers, fp32 logits/accumulation, plain-exp softmax.
__device__ __forceinline__ float4 load_msg(int u, int lane) {
    const __half2* p = (const __half2*)(g_emb_h + u * 128 + 4 * lane);
    __half2 m0 = p[0], m1 = p[1];
    float2 a = __half22float2(m0), b = __half22float2(m1);
    return make_float4(a.x, a.y, b.x, b.y);
}

__global__ void __launch_bounds__(256) k_gat(const float* __restrict__ bias,
                                             float* __restrict__ out) {
    int w = (blockIdx.x * blockDim.x + threadIdx.x) >> 5;
    int lane = threadIdx.x & 31;
    const int NW = Nn * (Gg / GC);
    if (w >= NW) return;
    int v = w >> 2;          // adjacent warps share v -> L1 hits on structure
    int gc = w & 3;          // graph chunk: graphs gc*4 .. gc*4+3
    int h = lane >> 3;

    int4 vx = *(const int4*)(g_xT + v * Gg + gc * GC);
    int vemb[GC] = {vx.x, vx.y, vx.z, vx.w};

    float adst[GC], s[GC];
    float4 acc[GC];
#pragma unroll
    for (int i = 0; i < GC; i++) {
        adst[i] = g_adst[vemb[i] * 4 + h];
        float a0 = g_asrc[vemb[i] * 4 + h] + adst[i];
        a0 = fmaxf(a0, NEG * a0);
        float e0 = __expf(a0);
        s[i] = e0;
        float4 m = load_msg(vemb[i], lane);
        acc[i] = make_float4(e0 * m.x, e0 * m.y, e0 * m.z, e0 * m.w);
    }

    int idx = g_row_ptr[v];
    int end = g_row_ptr[v + 1];
    for (; idx < end; idx++) {
        int j = g_edge_src[idx];
        int4 ux = *(const int4*)(g_xT + j * Gg + gc * GC);
        int u[GC] = {ux.x, ux.y, ux.z, ux.w};
        float4 m[GC];
        float a[GC];
#pragma unroll
        for (int i = 0; i < GC; i++) {
            a[i] = g_asrc[u[i] * 4 + h] + adst[i];
            m[i] = load_msg(u[i], lane);
        }
#pragma unroll
        for (int i = 0; i < GC; i++) {
            float ai = fmaxf(a[i], NEG * a[i]);
            float wi = __expf(ai);
            s[i] += wi;
            acc[i].x = fmaf(wi, m[i].x, acc[i].x);
            acc[i].y = fmaf(wi, m[i].y, acc[i].y);
            acc[i].z = fmaf(wi, m[i].z, acc[i].z);
            acc[i].w = fmaf(wi, m[i].w, acc[i].w);
        }
    }

    float4 b = *(const float4*)(bias + 4 * lane);
#pragma unroll
    for (int i = 0; i < GC; i++) {
        float inv = 1.f / (s[i] + 1e-16f);
        float4 o;
        o.x = fmaf(acc[i].x, inv, b.x);
        o.y = fmaf(acc[i].y, inv, b.y);
        o.z = fmaf(acc[i].z, inv, b.z);
        o.w = fmaf(acc[i].w, inv, b.w);
        int g = gc * GC + i;
        *(float4*)(out + ((size_t)g * Nn + v) * 128 + 4 * lane) = o;
    }
}

extern "C" void kernel_launch(void* const* d_in, const int* in_sizes, int n_in,
                              void* d_out, int out_size) {
    const int*   x     = (const int*)d_in[0];     // [B,DAYS,N] = [16,10000]
    const int*   adj   = (const int*)d_in[1];     // [2,E]
    const float* emb   = (const float*)d_in[2];   // [N,32]
    const float* W     = (const float*)d_in[3];   // [32,128]
    const float* att_s = (const float*)d_in[4];   // [4,32]
    const float* att_d = (const float*)d_in[5];   // [4,32]
    const float* bias  = (const float*)d_in[6];   // [128]
    float* out = (float*)d_out;                   // [16,10000,128]

    k_hist<<<(Ee + 255) / 256, 256>>>(adj);
    k_scan<<<1, 1024>>>();
    k_fill<<<(Ee + 255) / 256, 256>>>(adj);
    k_proj<<<Nn, 128>>>(emb, W, att_s, att_d, x);   // also: xT transpose + cursor reset

    int total_warps = Nn * (Gg / GC);
    k_gat<<<(total_warps * 32 + 255) / 256, 256>>>(bias, out);
}

// round 4
// speedup vs baseline: 1.3413x; 1.0900x over previous
#include <cuda_runtime.h>
#include <cuda_fp16.h>

// Problem constants (fixed by the reference)
#define Nn   10000      // nodes
#define Ee   80000      // edges (excl. self loops)
#define Gg   16         // B*DAYS graphs
#define HC   128        // H*C_OUT
#define NEG  0.2f
#define GC   4          // graphs per warp in k_gat
#define PR   8          // rows per block in k_proj

// ---- device scratch (allocation-free rule: __device__ globals) ----
__device__ __align__(16) __half g_emb_h[Nn * HC];     // fp16 projected embedding [N,128]
__device__ __align__(16) float g_asrc[Nn * 4];        // per-row src logits [N,H]
__device__ __align__(16) float g_adst[Nn * 4];        // per-row dst logits [N,H]
__device__ __align__(16) int g_xT[Nn * Gg];           // transposed x: [N,16]
__device__ __align__(16) float g_ws[32 * 8];          // fused W@att: [k,(src h0..3, dst h0..3)]
__device__ int g_row_ptr[Nn + 1];
__device__ int g_cursor[Nn];                          // INVARIANT: all-zero at kernel_launch entry
__device__ int g_edge_src[Ee];

// ---------------- CSR build ----------------
// g_cursor is zero on entry (zero-init at load; re-zeroed by k_proj each launch)
__global__ void k_hist(const int* __restrict__ adj) {
    int e = blockIdx.x * blockDim.x + threadIdx.x;
    if (e < Ee) atomicAdd(&g_cursor[adj[Ee + e]], 1);  // adj[1] = dst
}

// single-block: exclusive scan of g_cursor -> g_row_ptr (+copy), and compute g_ws
__global__ void k_scan(const float* __restrict__ W,
                       const float* __restrict__ att_s, const float* __restrict__ att_d) {
    const int CH = 10;  // 1024*10 >= 10000
    __shared__ int part[1024];
    int t = threadIdx.x;

    // side duty: ws[k][j] = sum_c W[k,h*32+c] * att_{src/dst}[h,c], j = (srcdst<<2)|h
    if (t < 256) {
        int k = t >> 3, j = t & 7, h = j & 3;
        const float* av = (j < 4) ? att_s : att_d;
        float acc = 0.f;
#pragma unroll
        for (int c = 0; c < 32; c++)
            acc = fmaf(W[k * 128 + h * 32 + c], av[h * 32 + c], acc);
        g_ws[k * 8 + j] = acc;
    }

    int base = t * CH;
    int loc[CH];
    int sum = 0;
#pragma unroll
    for (int i = 0; i < CH; i++) {
        int idx = base + i;
        int v = (idx < Nn) ? g_cursor[idx] : 0;
        loc[i] = sum;
        sum += v;
    }
    part[t] = sum;
    __syncthreads();
    for (int off = 1; off < 1024; off <<= 1) {
        int v = (t >= off) ? part[t - off] : 0;
        __syncthreads();
        part[t] += v;
        __syncthreads();
    }
    int prev = (t > 0) ? part[t - 1] : 0;
#pragma unroll
    for (int i = 0; i < CH; i++) {
        int idx = base + i;
        if (idx < Nn) {
            int p = prev + loc[i];
            g_row_ptr[idx] = p;
            g_cursor[idx] = p;
        }
    }
    if (t == 0) g_row_ptr[Nn] = part[1023];
}

__global__ void k_fill(const int* __restrict__ adj) {
    int e = blockIdx.x * blockDim.x + threadIdx.x;
    if (e < Ee) {
        int d = adj[Ee + e];
        int p = atomicAdd(&g_cursor[d], 1);
        g_edge_src[p] = adj[e];  // adj[0] = src
    }
}

// ---------------- projection (8 rows/block, W column in registers) ----------------
__global__ void __launch_bounds__(128) k_proj(const float* __restrict__ emb,
                                              const float* __restrict__ W,
                                              const int* __restrict__ x) {
    int n0 = blockIdx.x * PR;
    int c = threadIdx.x;  // channel 0..127

    // W column for this channel, once per block
    float wcol[32];
#pragma unroll
    for (int k = 0; k < 32; k++) wcol[k] = W[k * 128 + c];

    // 8 embedding rows, coalesced (256 floats / 128 threads)
    __shared__ float se[PR][32];
#pragma unroll
    for (int i = 0; i < 2; i++) {
        int idx = i * 128 + c;
        se[idx >> 5][idx & 31] = emb[n0 * 32 + idx];
    }

    // side duties: cursor reset + x transpose (8 consecutive n per graph g)
    if (c < PR) g_cursor[n0 + c] = 0;
    {
        int g = c >> 3, i = c & 7;  // g: 0..15, i: 0..7
        g_xT[(n0 + i) * Gg + g] = x[g * Nn + n0 + i];
    }
    __syncthreads();

    // main: projected embedding, fp16
#pragma unroll
    for (int r = 0; r < PR; r++) {
        float acc = 0.f;
#pragma unroll
        for (int k = 0; k < 32; k++) acc = fmaf(se[r][k], wcol[k], acc);
        g_emb_h[(n0 + r) * 128 + c] = __float2half(acc);
    }

    // logits via fused ws: 64 dots (8 rows x 8 cols)
    if (c < 64) {
        int r = c >> 3, j = c & 7, h = j & 3;
        float acc = 0.f;
#pragma unroll
        for (int k = 0; k < 32; k++) acc = fmaf(se[r][k], g_ws[k * 8 + j], acc);
        if (j < 4) g_asrc[(n0 + r) * 4 + h] = acc;
        else       g_adst[(n0 + r) * 4 + h] = acc;
    }
}

// ---------------- main GAT kernel: one warp per (4-graph chunk, dst node) ----------------
__device__ __forceinline__ float4 load_msg(int u, int lane) {
    const __half2* p = (const __half2*)(g_emb_h + u * 128 + 4 * lane);
    __half2 m0 = p[0], m1 = p[1];
    float2 a = __half22float2(m0), b = __half22float2(m1);
    return make_float4(a.x, a.y, b.x, b.y);
}

__global__ void __launch_bounds__(256) k_gat(const float* __restrict__ bias,
                                             float* __restrict__ out) {
    int w = (blockIdx.x * blockDim.x + threadIdx.x) >> 5;
    int lane = threadIdx.x & 31;
    const int NW = Nn * (Gg / GC);
    if (w >= NW) return;
    int v = w >> 2;          // adjacent warps share v -> L1 hits on structure
    int gc = w & 3;          // graph chunk: graphs gc*4 .. gc*4+3
    int h = lane >> 3;

    int4 vx = *(const int4*)(g_xT + v * Gg + gc * GC);
    int vemb[GC] = {vx.x, vx.y, vx.z, vx.w};

    float adst[GC], s[GC];
    float4 acc[GC];
#pragma unroll
    for (int i = 0; i < GC; i++) {
        adst[i] = g_adst[vemb[i] * 4 + h];
        float a0 = g_asrc[vemb[i] * 4 + h] + adst[i];
        a0 = fmaxf(a0, NEG * a0);
        float e0 = __expf(a0);
        s[i] = e0;
        float4 m = load_msg(vemb[i], lane);
        acc[i] = make_float4(e0 * m.x, e0 * m.y, e0 * m.z, e0 * m.w);
    }

    int idx = g_row_ptr[v];
    int end = g_row_ptr[v + 1];
    // software pipeline: next edge's xT prefetched while current gathers fly
    int4 ux = make_int4(0, 0, 0, 0);
    if (idx < end) {
        int j = g_edge_src[idx];
        ux = *(const int4*)(g_xT + j * Gg + gc * GC);
    }
    while (idx < end) {
        int nidx = idx + 1;
        int4 uxn = make_int4(0, 0, 0, 0);
        if (nidx < end) {
            int jn = g_edge_src[nidx];
            uxn = *(const int4*)(g_xT + jn * Gg + gc * GC);
        }
        int u[GC] = {ux.x, ux.y, ux.z, ux.w};
        float a[GC];
        float4 m[GC];
#pragma unroll
        for (int i = 0; i < GC; i++) {
            a[i] = g_asrc[u[i] * 4 + h] + adst[i];
            m[i] = load_msg(u[i], lane);
        }
#pragma unroll
        for (int i = 0; i < GC; i++) {
            float ai = fmaxf(a[i], NEG * a[i]);
            float wi = __expf(ai);
            s[i] += wi;
            acc[i].x = fmaf(wi, m[i].x, acc[i].x);
            acc[i].y = fmaf(wi, m[i].y, acc[i].y);
            acc[i].z = fmaf(wi, m[i].z, acc[i].z);
            acc[i].w = fmaf(wi, m[i].w, acc[i].w);
        }
        ux = uxn;
        idx = nidx;
    }

    float4 b = *(const float4*)(bias + 4 * lane);
#pragma unroll
    for (int i = 0; i < GC; i++) {
        float inv = 1.f / (s[i] + 1e-16f);
        float4 o;
        o.x = fmaf(acc[i].x, inv, b.x);
        o.y = fmaf(acc[i].y, inv, b.y);
        o.z = fmaf(acc[i].z, inv, b.z);
        o.w = fmaf(acc[i].w, inv, b.w);
        int g = gc * GC + i;
        *(float4*)(out + ((size_t)g * Nn + v) * 128 + 4 * lane) = o;
    }
}

extern "C" void kernel_launch(void* const* d_in, const int* in_sizes, int n_in,
                              void* d_out, int out_size) {
    const int*   x     = (const int*)d_in[0];     // [B,DAYS,N] = [16,10000]
    const int*   adj   = (const int*)d_in[1];     // [2,E]
    const float* emb   = (const float*)d_in[2];   // [N,32]
    const float* W     = (const float*)d_in[3];   // [32,128]
    const float* att_s = (const float*)d_in[4];   // [4,32]
    const float* att_d = (const float*)d_in[5];   // [4,32]
    const float* bias  = (const float*)d_in[6];   // [128]
    float* out = (float*)d_out;                   // [16,10000,128]

    k_hist<<<(Ee + 255) / 256, 256>>>(adj);
    k_scan<<<1, 1024>>>(W, att_s, att_d);          // also computes g_ws
    k_fill<<<(Ee + 255) / 256, 256>>>(adj);
    k_proj<<<Nn / PR, 128>>>(emb, W, x);           // also: xT transpose + cursor reset

    int total_warps = Nn * (Gg / GC);
    k_gat<<<(total_warps * 32 + 255) / 256, 256>>>(bias, out);
}